// round 7
// baseline (speedup 1.0000x reference)
#include <cuda_runtime.h>

#define DIN 784
#define H 32
#define KC 16      /* k per chunk; chunk offset 64B -> cp.async aligned */
#define NCHUNK 49  /* 784 / 16 */
#define NBUF 3     /* triple-buffered pipeline */
#define TM 64      /* rows per block */
#define NTH 64     /* 2 warps */
#define SXS 20     /* x row stride: 80B (16B-aligned) + conflict-free LDS.128 */
#define SHS 40     /* h row stride (16B-aligned) */

typedef unsigned long long ull;

__device__ float2 g_U[256];   // U[j][b] row-major, complex

__device__ __forceinline__ void fma2(ull &d, ull a, ull b){
    asm("fma.rn.f32x2 %0, %1, %2, %0;" : "+l"(d) : "l"(a), "l"(b));
}
__device__ __forceinline__ ull dup2(float v){
    ull r; asm("mov.b64 %0, {%1, %1};" : "=l"(r) : "f"(v)); return r;
}
__device__ __forceinline__ float2 unpack2(ull v){
    float2 r; asm("mov.b64 {%0, %1}, %2;" : "=f"(r.x), "=f"(r.y) : "l"(v)); return r;
}
__device__ __forceinline__ float2 cmul(float2 a, float2 b){
    return make_float2(a.x*b.x - a.y*b.y, a.x*b.y + a.y*b.x);
}
__device__ __forceinline__ void cp16(float* dst, const float* src){
    unsigned d = (unsigned)__cvta_generic_to_shared(dst);
    asm volatile("cp.async.cg.shared.global [%0], [%1], 16;" :: "r"(d), "l"(src));
}

// ---------------------------------------------------------------------------
// Kernel A: build the 16x16 complex unitary. Runs once, 1 block, cheap.
// ---------------------------------------------------------------------------
__global__ void build_U_kernel(const float* __restrict__ shared_w,
                               const float* __restrict__ task_w){
    __shared__ float2 U[16][16];
    int tid = threadIdx.x;
    for (int i = tid; i < 256; i += 128)
        U[i>>4][i&15] = make_float2((i>>4)==(i&15) ? 1.f : 0.f, 0.f);
    __syncthreads();

    for (int l = 0; l < 3; l++){
        const float* wp = (l < 2) ? (shared_w + l*12) : task_w;
        for (int wire = 0; wire < 4; wire++){
            float phi = wp[wire*3+0], th = wp[wire*3+1], om = wp[wire*3+2];
            float ch = cosf(0.5f*th), shn = sinf(0.5f*th);
            float a = 0.5f*(phi+om), d = 0.5f*(phi-om);
            float sa, ca, sd, cd;
            sincosf(a, &sa, &ca); sincosf(d, &sd, &cd);
            float2 m00 = make_float2( ca*ch, -sa*ch);
            float2 m01 = make_float2(-cd*shn, -sd*shn);
            float2 m10 = make_float2( cd*shn, -sd*shn);
            float2 m11 = make_float2( ca*ch,  sa*ch);
            int bp = 3 - wire;
            {
                int p = tid >> 4, col = tid & 15;
                int r0 = ((p >> bp) << (bp+1)) | (p & ((1<<bp)-1));
                int r1 = r0 | (1 << bp);
                float2 u0 = U[r0][col], u1 = U[r1][col];
                float2 t0 = cmul(m00,u0), t1 = cmul(m01,u1);
                float2 t2 = cmul(m10,u0), t3 = cmul(m11,u1);
                U[r0][col] = make_float2(t0.x+t1.x, t0.y+t1.y);
                U[r1][col] = make_float2(t2.x+t3.x, t2.y+t3.y);
            }
            __syncthreads();
        }
        int r = (l == 1) ? 2 : 1;
        for (int i = 0; i < 4; i++){
            int c = i, t = (i + r) & 3;
            int pc = 3 - c, pt = 3 - t;
            if (tid < 64){
                int idx = tid >> 4, col = tid & 15;
                int rem0 = -1, rem1 = -1;
                for (int bit = 3; bit >= 0; bit--)
                    if (bit != pc && bit != pt){ if (rem0 < 0) rem0 = bit; else rem1 = bit; }
                int b  = (1 << pc) | (((idx>>1)&1) << rem0) | ((idx&1) << rem1);
                int b2 = b | (1 << pt);
                float2 tmp = U[b][col]; U[b][col] = U[b2][col]; U[b2][col] = tmp;
            }
            __syncthreads();
        }
    }
    for (int i = tid; i < 256; i += 128) g_U[i] = U[i>>4][i&15];
}

// ---------------------------------------------------------------------------
// Kernel B: fused GEMM(65536x784x32) + epilogue chain.
// 64 threads / 64 rows per block; thread tile = 4 rows x 8 cols.
// Triple-buffered cp.async; x via LDS.128 (4k per load), w via LDS.128 bcast.
// ---------------------------------------------------------------------------
__global__ void __launch_bounds__(NTH, 8) fused_kernel(
    const float* __restrict__ x,   const float* __restrict__ w1,
    const float* __restrict__ b1,  const float* __restrict__ lng,
    const float* __restrict__ lnb, const float* __restrict__ w2,
    const float* __restrict__ b2,  const float* __restrict__ pw,
    const float* __restrict__ pb,  float2* __restrict__ out)
{
    __shared__ __align__(16) float  s_x[NBUF][TM*SXS];  // 3x5KB; h tile reuse
    __shared__ __align__(16) float  s_w[NBUF][KC*H];    // 3x2KB
    __shared__ __align__(16) float2 s_U[256];
    __shared__ float  s_b1[H], s_g[H], s_b[H], s_w2[H*4], s_b2[4], s_pw[8], s_pb[2];

    const int tid = threadIdx.x;
    const int tc  = tid & 3;        // col group: cols tc*8 .. tc*8+7
    const int tr  = tid >> 2;       // row-group offset: rows j*16 + tr, j=0..3
    const int row0 = blockIdx.x * TM;

    // stage tiny params + U (g_U = 128 float4; it<2 with NTH=64)
    #pragma unroll
    for (int it = 0; it < 2; it++)
        ((float4*)s_U)[it*NTH + tid] = ((const float4*)g_U)[it*NTH + tid];
    if (tid < H) { s_b1[tid] = b1[tid]; s_g[tid] = lng[tid]; s_b[tid] = lnb[tid]; }
    #pragma unroll
    for (int it = 0; it < 2; it++) s_w2[it*NTH + tid] = w2[it*NTH + tid];
    if (tid < 4)  s_b2[tid] = b2[tid];
    if (tid < 8)  s_pw[tid] = pw[tid];
    if (tid < 2)  s_pb[tid] = pb[tid];

    // ---- async stage of one chunk into buffer `buf` ----
    auto stage = [&](int ch, int buf){
        const int kc0 = ch * KC;
        #pragma unroll
        for (int it = 0; it < 4; it++){
            int i = it*NTH + tid;          // 0..255
            int row = i >> 2, seg = i & 3; // 64 rows x 4 float4 segs
            cp16(&s_x[buf][row*SXS + seg*4],
                 &x[(size_t)(row0+row)*DIN + kc0 + seg*4]);
        }
        #pragma unroll
        for (int it = 0; it < 2; it++){
            int i = it*NTH + tid;          // 0..127 float4s
            cp16(&s_w[buf][i*4], &w1[(size_t)kc0*H + i*4]);
        }
        asm volatile("cp.async.commit_group;");
    };

    ull acc[4][4];
    #pragma unroll
    for (int j = 0; j < 4; j++)
        #pragma unroll
        for (int cp = 0; cp < 4; cp++) acc[j][cp] = 0ull;

    stage(0, 0);
    stage(1, 1);
    stage(2, 2);

    #pragma unroll 1
    for (int ch = 0; ch < NCHUNK; ch++){
        asm volatile("cp.async.wait_group 2;");   // chunk ch's group complete
        __syncthreads();
        const int buf = ch % NBUF;
        const float* xb = &s_x[buf][tr*SXS];
        const float* wb = s_w[buf];

        #pragma unroll
        for (int k4 = 0; k4 < KC/4; k4++){
            const int k0 = 4*k4;
            // x: 4 LDS.128 (rows j*16+tr); offsets tr*20+k0 mod 32 cover all
            // 32 banks in disjoint 4-word groups -> conflict-free
            float4 xv[4];
            #pragma unroll
            for (int j = 0; j < 4; j++)
                xv[j] = *(const float4*)(xb + j*16*SXS + k0);
            #pragma unroll
            for (int kk = 0; kk < 4; kk++){
                float4 wa = *(const float4*)&wb[(k0+kk)*H + tc*8];
                float4 wv = *(const float4*)&wb[(k0+kk)*H + tc*8 + 4];
                ull w0 = ((const ull*)&wa)[0], w1r = ((const ull*)&wa)[1];
                ull w2r = ((const ull*)&wv)[0], w3r = ((const ull*)&wv)[1];
                #pragma unroll
                for (int j = 0; j < 4; j++){
                    ull xd = dup2(((const float*)&xv[j])[kk]);
                    fma2(acc[j][0], xd, w0);  fma2(acc[j][1], xd, w1r);
                    fma2(acc[j][2], xd, w2r); fma2(acc[j][3], xd, w3r);
                }
            }
        }
        __syncthreads();                    // reads of buf done before overwrite
        if (ch + NBUF < NCHUNK) stage(ch + NBUF, buf);
        else asm volatile("cp.async.commit_group;");  // empty group keeps FIFO exact
    }

    asm volatile("cp.async.wait_group 0;");
    __syncthreads();

    float* s_h = &s_x[0][0];                // 64*40 = 2560 <= 3*1280 floats

    // bias + ReLU, scatter into h tile (row = j*16 + tr)
    #pragma unroll
    for (int j = 0; j < 4; j++){
        int row = j*16 + tr;
        #pragma unroll
        for (int cp = 0; cp < 4; cp++){
            float2 p = unpack2(acc[j][cp]);
            int col = tc*8 + cp*2;
            float v0 = p.x + s_b1[col];     v0 = v0 > 0.f ? v0 : 0.f;
            float v1 = p.y + s_b1[col+1];   v1 = v1 > 0.f ? v1 : 0.f;
            s_h[row*SHS + col]     = v0;
            s_h[row*SHS + col + 1] = v1;
        }
    }
    __syncthreads();

    // per-row epilogue: one thread = one row (TM == NTH)
    {
        float h[32];
        const float4* hr = (const float4*)&s_h[tid*SHS];
        #pragma unroll
        for (int q = 0; q < 8; q++){
            float4 v = hr[q];
            h[q*4]=v.x; h[q*4+1]=v.y; h[q*4+2]=v.z; h[q*4+3]=v.w;
        }
        float mu = 0.f;
        #pragma unroll
        for (int c = 0; c < 32; c++) mu += h[c];
        mu *= (1.f/32.f);
        float var = 0.f;
        #pragma unroll
        for (int c = 0; c < 32; c++){ float d = h[c]-mu; var += d*d; }
        var *= (1.f/32.f);
        float inv = rsqrtf(var + 1e-5f);

        float z0 = s_b2[0], z1 = s_b2[1], z2 = s_b2[2], z3 = s_b2[3];
        #pragma unroll
        for (int c = 0; c < 32; c++){
            float hn = (h[c]-mu)*inv*s_g[c] + s_b[c];
            z0 += hn * s_w2[c*4+0];
            z1 += hn * s_w2[c*4+1];
            z2 += hn * s_w2[c*4+2];
            z3 += hn * s_w2[c*4+3];
        }
        float cs[4], sn[4], zz;
        zz = tanhf(z0) * 1.5707963267948966f; sincosf(zz, &sn[0], &cs[0]);
        zz = tanhf(z1) * 1.5707963267948966f; sincosf(zz, &sn[1], &cs[1]);
        zz = tanhf(z2) * 1.5707963267948966f; sincosf(zz, &sn[2], &cs[2]);
        zz = tanhf(z3) * 1.5707963267948966f; sincosf(zz, &sn[3], &cs[3]);

        float t01[4], t23[4], psi[16];
        t01[0]=cs[0]*cs[1]; t01[1]=cs[0]*sn[1]; t01[2]=sn[0]*cs[1]; t01[3]=sn[0]*sn[1];
        t23[0]=cs[2]*cs[3]; t23[1]=cs[2]*sn[3]; t23[2]=sn[2]*cs[3]; t23[3]=sn[2]*sn[3];
        #pragma unroll
        for (int bb = 0; bb < 16; bb++) psi[bb] = t01[bb>>2]*t23[bb&3];

        float e0=0.f, e1=0.f, e2=0.f, e3=0.f;
        #pragma unroll 4
        for (int j = 0; j < 16; j++){
            float re = 0.f, im = 0.f;
            #pragma unroll
            for (int bb = 0; bb < 16; bb++){
                float2 u = s_U[j*16 + bb];
                re += psi[bb]*u.x;
                im += psi[bb]*u.y;
            }
            float p = re*re + im*im;
            e0 += (j & 8) ? -p : p;
            e1 += (j & 4) ? -p : p;
            e2 += (j & 2) ? -p : p;
            e3 += (j & 1) ? -p : p;
        }
        float o0 = s_pb[0] + e0*s_pw[0] + e1*s_pw[2] + e2*s_pw[4] + e3*s_pw[6];
        float o1 = s_pb[1] + e0*s_pw[1] + e1*s_pw[3] + e2*s_pw[5] + e3*s_pw[7];
        out[row0 + tid] = make_float2(o0, o1);
    }
}

// ---------------------------------------------------------------------------
extern "C" void kernel_launch(void* const* d_in, const int* in_sizes, int n_in,
                              void* d_out, int out_size)
{
    const float* x   = (const float*)d_in[0];
    const float* w1  = (const float*)d_in[1];
    const float* b1  = (const float*)d_in[2];
    const float* lng = (const float*)d_in[3];
    const float* lnb = (const float*)d_in[4];
    const float* w2  = (const float*)d_in[5];
    const float* b2  = (const float*)d_in[6];
    const float* sw  = (const float*)d_in[7];
    const float* tw  = (const float*)d_in[8];
    const float* pw  = (const float*)d_in[9];
    const float* pb  = (const float*)d_in[10];
    (void)n_in; (void)out_size;

    int rows = in_sizes[0] / DIN;

    build_U_kernel<<<1, 128>>>(sw, tw);
    fused_kernel<<<rows / TM, NTH>>>(x, w1, b1, lng, lnb, w2, b2, pw, pb,
                                     (float2*)d_out);
}

// round 8
// speedup vs baseline: 1.0463x; 1.0463x over previous
#include <cuda_runtime.h>

#define DIN 784
#define H 32
#define KC 16      /* k per chunk; chunk offset 64B -> cp.async aligned */
#define NCHUNK 49  /* 784 / 16 */
#define NBUF 3     /* triple-buffered pipeline */
#define TM 64      /* rows per block */
#define NTH 32     /* ONE warp per block: no block barriers */
#define SXS 20     /* x row stride: 80B (16B-aligned) + conflict-free LDS.128 */
#define SHS 40     /* h row stride (16B-aligned) */

typedef unsigned long long ull;

__device__ float2 g_U[256];   // U[j][b] row-major, complex

__device__ __forceinline__ void fma2(ull &d, ull a, ull b){
    asm("fma.rn.f32x2 %0, %1, %2, %0;" : "+l"(d) : "l"(a), "l"(b));
}
__device__ __forceinline__ ull dup2(float v){
    ull r; asm("mov.b64 %0, {%1, %1};" : "=l"(r) : "f"(v)); return r;
}
__device__ __forceinline__ float2 unpack2(ull v){
    float2 r; asm("mov.b64 {%0, %1}, %2;" : "=f"(r.x), "=f"(r.y) : "l"(v)); return r;
}
__device__ __forceinline__ float2 cmul(float2 a, float2 b){
    return make_float2(a.x*b.x - a.y*b.y, a.x*b.y + a.y*b.x);
}
__device__ __forceinline__ void cp16(float* dst, const float* src){
    unsigned d = (unsigned)__cvta_generic_to_shared(dst);
    asm volatile("cp.async.cg.shared.global [%0], [%1], 16;" :: "r"(d), "l"(src));
}

// ---------------------------------------------------------------------------
// Kernel A: build the 16x16 complex unitary. Runs once, 1 block, cheap.
// ---------------------------------------------------------------------------
__global__ void build_U_kernel(const float* __restrict__ shared_w,
                               const float* __restrict__ task_w){
    __shared__ float2 U[16][16];
    int tid = threadIdx.x;
    for (int i = tid; i < 256; i += 128)
        U[i>>4][i&15] = make_float2((i>>4)==(i&15) ? 1.f : 0.f, 0.f);
    __syncthreads();

    for (int l = 0; l < 3; l++){
        const float* wp = (l < 2) ? (shared_w + l*12) : task_w;
        for (int wire = 0; wire < 4; wire++){
            float phi = wp[wire*3+0], th = wp[wire*3+1], om = wp[wire*3+2];
            float ch = cosf(0.5f*th), shn = sinf(0.5f*th);
            float a = 0.5f*(phi+om), d = 0.5f*(phi-om);
            float sa, ca, sd, cd;
            sincosf(a, &sa, &ca); sincosf(d, &sd, &cd);
            float2 m00 = make_float2( ca*ch, -sa*ch);
            float2 m01 = make_float2(-cd*shn, -sd*shn);
            float2 m10 = make_float2( cd*shn, -sd*shn);
            float2 m11 = make_float2( ca*ch,  sa*ch);
            int bp = 3 - wire;
            {
                int p = tid >> 4, col = tid & 15;
                int r0 = ((p >> bp) << (bp+1)) | (p & ((1<<bp)-1));
                int r1 = r0 | (1 << bp);
                float2 u0 = U[r0][col], u1 = U[r1][col];
                float2 t0 = cmul(m00,u0), t1 = cmul(m01,u1);
                float2 t2 = cmul(m10,u0), t3 = cmul(m11,u1);
                U[r0][col] = make_float2(t0.x+t1.x, t0.y+t1.y);
                U[r1][col] = make_float2(t2.x+t3.x, t2.y+t3.y);
            }
            __syncthreads();
        }
        int r = (l == 1) ? 2 : 1;
        for (int i = 0; i < 4; i++){
            int c = i, t = (i + r) & 3;
            int pc = 3 - c, pt = 3 - t;
            if (tid < 64){
                int idx = tid >> 4, col = tid & 15;
                int rem0 = -1, rem1 = -1;
                for (int bit = 3; bit >= 0; bit--)
                    if (bit != pc && bit != pt){ if (rem0 < 0) rem0 = bit; else rem1 = bit; }
                int b  = (1 << pc) | (((idx>>1)&1) << rem0) | ((idx&1) << rem1);
                int b2 = b | (1 << pt);
                float2 tmp = U[b][col]; U[b][col] = U[b2][col]; U[b2][col] = tmp;
            }
            __syncthreads();
        }
    }
    for (int i = tid; i < 256; i += 128) g_U[i] = U[i>>4][i&15];
}

// ---------------------------------------------------------------------------
// Kernel B: fused GEMM(65536x784x32) + epilogue chain.
// ONE warp per block, 64 rows. Thread tile = 8 rows x 8 cols (rows j*8+rg).
// Triple-buffered cp.async; warp-scope sync only (no bar.sync in main loop).
// ---------------------------------------------------------------------------
__global__ void __launch_bounds__(NTH, 8) fused_kernel(
    const float* __restrict__ x,   const float* __restrict__ w1,
    const float* __restrict__ b1,  const float* __restrict__ lng,
    const float* __restrict__ lnb, const float* __restrict__ w2,
    const float* __restrict__ b2,  const float* __restrict__ pw,
    const float* __restrict__ pb,  float2* __restrict__ out)
{
    __shared__ __align__(16) float  s_x[NBUF][TM*SXS];  // 3x5KB; h tile reuse
    __shared__ __align__(16) float  s_w[NBUF][KC*H];    // 3x2KB
    __shared__ __align__(16) float2 s_U[256];
    __shared__ float  s_b1[H], s_g[H], s_b[H], s_w2[H*4], s_b2[4], s_pw[8], s_pb[2];

    const int tid = threadIdx.x;
    const int cg  = tid & 3;        // col group: cols cg*8 .. cg*8+7
    const int rg  = tid >> 2;       // row offset: rows j*8 + rg, j=0..7
    const int row0 = blockIdx.x * TM;

    // stage tiny params + U (g_U = 128 float4; it<4 with NTH=32)
    #pragma unroll
    for (int it = 0; it < 4; it++)
        ((float4*)s_U)[it*NTH + tid] = ((const float4*)g_U)[it*NTH + tid];
    s_b1[tid] = b1[tid]; s_g[tid] = lng[tid]; s_b[tid] = lnb[tid];
    #pragma unroll
    for (int it = 0; it < 4; it++) s_w2[it*NTH + tid] = w2[it*NTH + tid];
    if (tid < 4)  s_b2[tid] = b2[tid];
    if (tid < 8)  s_pw[tid] = pw[tid];
    if (tid < 2)  s_pb[tid] = pb[tid];

    // ---- async stage of one chunk into buffer `buf` ----
    auto stage = [&](int ch, int buf){
        const int kc0 = ch * KC;
        #pragma unroll
        for (int it = 0; it < 8; it++){
            int i = it*NTH + tid;          // 0..255
            int row = i >> 2, seg = i & 3; // 64 rows x 4 float4 segs
            cp16(&s_x[buf][row*SXS + seg*4],
                 &x[(size_t)(row0+row)*DIN + kc0 + seg*4]);
        }
        #pragma unroll
        for (int it = 0; it < 4; it++){
            int i = it*NTH + tid;          // 0..127 float4s
            cp16(&s_w[buf][i*4], &w1[(size_t)kc0*H + i*4]);
        }
        asm volatile("cp.async.commit_group;");
    };

    ull acc[8][4];
    #pragma unroll
    for (int j = 0; j < 8; j++)
        #pragma unroll
        for (int cp = 0; cp < 4; cp++) acc[j][cp] = 0ull;

    stage(0, 0);
    stage(1, 1);
    stage(2, 2);

    #pragma unroll 1
    for (int ch = 0; ch < NCHUNK; ch++){
        asm volatile("cp.async.wait_group 2;");   // own group done
        __syncwarp();                             // cross-lane visibility
        const int buf = ch % NBUF;
        const float* xb = &s_x[buf][rg*SXS];
        const float* wb = s_w[buf];

        #pragma unroll
        for (int k4 = 0; k4 < KC/4; k4++){
            const int k0 = 4*k4;
            // x: 8 LDS.128; lane offsets rg*20 mod 32 disjoint -> conflict-free
            float4 xv[8];
            #pragma unroll
            for (int j = 0; j < 8; j++)
                xv[j] = *(const float4*)(xb + j*8*SXS + k0);
            #pragma unroll
            for (int kk = 0; kk < 4; kk++){
                float4 wa = *(const float4*)&wb[(k0+kk)*H + cg*8];
                float4 wv = *(const float4*)&wb[(k0+kk)*H + cg*8 + 4];
                ull w0 = ((const ull*)&wa)[0], w1r = ((const ull*)&wa)[1];
                ull w2r = ((const ull*)&wv)[0], w3r = ((const ull*)&wv)[1];
                #pragma unroll
                for (int j = 0; j < 8; j++){
                    ull xd = dup2(((const float*)&xv[j])[kk]);
                    fma2(acc[j][0], xd, w0);  fma2(acc[j][1], xd, w1r);
                    fma2(acc[j][2], xd, w2r); fma2(acc[j][3], xd, w3r);
                }
            }
        }
        __syncwarp();                       // lane reads of buf done
        if (ch + NBUF < NCHUNK) stage(ch + NBUF, buf);
        else asm volatile("cp.async.commit_group;");  // keep FIFO accounting
    }

    asm volatile("cp.async.wait_group 0;");
    __syncwarp();

    float* s_h = &s_x[0][0];                // 64*40 = 2560 <= 3*1280 floats

    // bias + ReLU, scatter into h tile (row = j*8 + rg)
    #pragma unroll
    for (int j = 0; j < 8; j++){
        int row = j*8 + rg;
        #pragma unroll
        for (int cp = 0; cp < 4; cp++){
            float2 p = unpack2(acc[j][cp]);
            int col = cg*8 + cp*2;
            float v0 = p.x + s_b1[col];     v0 = v0 > 0.f ? v0 : 0.f;
            float v1 = p.y + s_b1[col+1];   v1 = v1 > 0.f ? v1 : 0.f;
            s_h[row*SHS + col]     = v0;
            s_h[row*SHS + col + 1] = v1;
        }
    }
    __syncwarp();

    // per-row epilogue: thread handles rows {tid, tid+32}
    #pragma unroll
    for (int rr = 0; rr < 2; rr++){
        const int r = tid + rr*NTH;
        float h[32];
        const float4* hr = (const float4*)&s_h[r*SHS];
        #pragma unroll
        for (int q = 0; q < 8; q++){
            float4 v = hr[q];
            h[q*4]=v.x; h[q*4+1]=v.y; h[q*4+2]=v.z; h[q*4+3]=v.w;
        }
        float mu = 0.f;
        #pragma unroll
        for (int c = 0; c < 32; c++) mu += h[c];
        mu *= (1.f/32.f);
        float var = 0.f;
        #pragma unroll
        for (int c = 0; c < 32; c++){ float d = h[c]-mu; var += d*d; }
        var *= (1.f/32.f);
        float inv = rsqrtf(var + 1e-5f);

        float z0 = s_b2[0], z1 = s_b2[1], z2 = s_b2[2], z3 = s_b2[3];
        #pragma unroll
        for (int c = 0; c < 32; c++){
            float hn = (h[c]-mu)*inv*s_g[c] + s_b[c];
            z0 += hn * s_w2[c*4+0];
            z1 += hn * s_w2[c*4+1];
            z2 += hn * s_w2[c*4+2];
            z3 += hn * s_w2[c*4+3];
        }
        float cs[4], sn[4], zz;
        zz = tanhf(z0) * 1.5707963267948966f; sincosf(zz, &sn[0], &cs[0]);
        zz = tanhf(z1) * 1.5707963267948966f; sincosf(zz, &sn[1], &cs[1]);
        zz = tanhf(z2) * 1.5707963267948966f; sincosf(zz, &sn[2], &cs[2]);
        zz = tanhf(z3) * 1.5707963267948966f; sincosf(zz, &sn[3], &cs[3]);

        float t01[4], t23[4], psi[16];
        t01[0]=cs[0]*cs[1]; t01[1]=cs[0]*sn[1]; t01[2]=sn[0]*cs[1]; t01[3]=sn[0]*sn[1];
        t23[0]=cs[2]*cs[3]; t23[1]=cs[2]*sn[3]; t23[2]=sn[2]*cs[3]; t23[3]=sn[2]*sn[3];
        #pragma unroll
        for (int bb = 0; bb < 16; bb++) psi[bb] = t01[bb>>2]*t23[bb&3];

        float e0=0.f, e1=0.f, e2=0.f, e3=0.f;
        #pragma unroll 4
        for (int j = 0; j < 16; j++){
            float re = 0.f, im = 0.f;
            #pragma unroll
            for (int bb = 0; bb < 16; bb++){
                float2 u = s_U[j*16 + bb];
                re += psi[bb]*u.x;
                im += psi[bb]*u.y;
            }
            float p = re*re + im*im;
            e0 += (j & 8) ? -p : p;
            e1 += (j & 4) ? -p : p;
            e2 += (j & 2) ? -p : p;
            e3 += (j & 1) ? -p : p;
        }
        float o0 = s_pb[0] + e0*s_pw[0] + e1*s_pw[2] + e2*s_pw[4] + e3*s_pw[6];
        float o1 = s_pb[1] + e0*s_pw[1] + e1*s_pw[3] + e2*s_pw[5] + e3*s_pw[7];
        out[row0 + r] = make_float2(o0, o1);
    }
}

// ---------------------------------------------------------------------------
extern "C" void kernel_launch(void* const* d_in, const int* in_sizes, int n_in,
                              void* d_out, int out_size)
{
    const float* x   = (const float*)d_in[0];
    const float* w1  = (const float*)d_in[1];
    const float* b1  = (const float*)d_in[2];
    const float* lng = (const float*)d_in[3];
    const float* lnb = (const float*)d_in[4];
    const float* w2  = (const float*)d_in[5];
    const float* b2  = (const float*)d_in[6];
    const float* sw  = (const float*)d_in[7];
    const float* tw  = (const float*)d_in[8];
    const float* pw  = (const float*)d_in[9];
    const float* pb  = (const float*)d_in[10];
    (void)n_in; (void)out_size;

    int rows = in_sizes[0] / DIN;

    build_U_kernel<<<1, 128>>>(sw, tw);
    fused_kernel<<<rows / TM, NTH>>>(x, w1, b1, lng, lnb, w2, b2, pw, pb,
                                     (float2*)d_out);
}